// round 13
// baseline (speedup 1.0000x reference)
#include <cuda_runtime.h>
#include <cstdint>

#define BATCH 4
#define SEQ   2048
#define NH    16
#define DH    64
#define DM    1024
#define MROWS (BATCH*SEQ)

__device__ float g_q[(size_t)BATCH*NH*SEQ*DH];
__device__ float g_k[(size_t)BATCH*NH*SEQ*DH];
__device__ float g_v[(size_t)BATCH*NH*SEQ*DH];
__device__ float g_o[(size_t)MROWS*DM];
__device__ float g_xr[(size_t)MROWS*DM];     // rounded X
__device__ float g_wrt[(size_t)3*DM*DM];     // rounded+transposed QKV W: [wz][h*64+d][m]
__device__ float g_owt[(size_t)DM*DM];       // rounded+transposed O W: [n][k]

__device__ __forceinline__ uint32_t f2tf(float x) {
    uint32_t u;
    asm("cvt.rna.tf32.f32 %0, %1;" : "=r"(u) : "f"(x));
    return u;
}
__device__ __forceinline__ float f2tff(float x) { return __uint_as_float(f2tf(x)); }

__device__ __forceinline__ void mma_tf32(float* c,
    uint32_t a0, uint32_t a1, uint32_t a2, uint32_t a3,
    uint32_t b0, uint32_t b1)
{
    asm volatile(
        "mma.sync.aligned.m16n8k8.row.col.f32.tf32.tf32.f32 "
        "{%0,%1,%2,%3}, {%4,%5,%6,%7}, {%8,%9}, {%0,%1,%2,%3};"
        : "+f"(c[0]), "+f"(c[1]), "+f"(c[2]), "+f"(c[3])
        : "r"(a0), "r"(a1), "r"(a2), "r"(a3), "r"(b0), "r"(b1));
}

__device__ __forceinline__ void cp16(uint32_t sdst, const float* gsrc) {
    asm volatile("cp.async.cg.shared.global [%0], [%1], 16;"
                 :: "r"(sdst), "l"(gsrc) : "memory");
}
#define CP_COMMIT() asm volatile("cp.async.commit_group;" ::: "memory")
#define CP_WAIT(n)  asm volatile("cp.async.wait_group %0;" :: "n"(n) : "memory")

__device__ __forceinline__ void ldsm4(uint32_t& d0, uint32_t& d1,
                                      uint32_t& d2, uint32_t& d3, uint32_t addr)
{
    asm volatile("ldmatrix.sync.aligned.m8n8.x4.shared.b16 {%0,%1,%2,%3}, [%4];"
                 : "=r"(d0), "=r"(d1), "=r"(d2), "=r"(d3) : "r"(addr));
}

// ---------------------------------------------------------------------------
// prep_x: round X once (grid-stride)
// ---------------------------------------------------------------------------
__global__ __launch_bounds__(256) void prep_x(const float* __restrict__ X)
{
    const size_t n = (size_t)MROWS * DM;
    const size_t stride = (size_t)gridDim.x * blockDim.x * 4;
    for (size_t i = ((size_t)blockIdx.x * blockDim.x + threadIdx.x) * 4; i < n; i += stride) {
        float4 v = *(const float4*)&X[i];
        v.x = f2tff(v.x); v.y = f2tff(v.y); v.z = f2tff(v.z); v.w = f2tff(v.w);
        *(float4*)&g_xr[i] = v;
    }
}

// ---------------------------------------------------------------------------
// prep_w: transpose + round weights. z<48: QKV per head; z=48: O weights.
// (transpose indexing identical to the R9 prep, which passed correctness)
// ---------------------------------------------------------------------------
__global__ __launch_bounds__(256) void prep_w(
    const float* __restrict__ Qw, const float* __restrict__ Kw,
    const float* __restrict__ Vw, const float* __restrict__ Ow)
{
    __shared__ float t[32][33];
    const int z = blockIdx.z;
    const float* src; float* dst; int sC, dC;
    int r0 = blockIdx.x * 32, c0 = blockIdx.y * 32;
    if (z < 48) {
        if (blockIdx.y >= 2) return;               // d dimension only 64 wide
        int wz = z >> 4, h = z & 15;
        src = (wz == 0 ? Qw : wz == 1 ? Kw : Vw) + (size_t)h * DM * DH;
        dst = g_wrt + (size_t)wz * DM * DM + (size_t)h * DH * DM;
        sC = DH; dC = DM;
    } else {
        src = Ow; dst = g_owt; sC = DM; dC = DM;
    }
    const int tx = threadIdx.x & 31, ty0 = threadIdx.x >> 5;
#pragma unroll
    for (int i = 0; i < 4; i++)
        t[ty0 + i * 8][tx] = src[(size_t)(r0 + ty0 + i * 8) * sC + c0 + tx];
    __syncthreads();
#pragma unroll
    for (int i = 0; i < 4; i++)
        dst[(size_t)(c0 + ty0 + i * 8) * dC + r0 + tx] = f2tff(t[tx][ty0 + i * 8]);
}

// ---------------------------------------------------------------------------
// GEMM: block 128x128, warp 32x64, 3-stage cp.async, ldmatrix fragments.
// A tile [128 m][32 k], B tile [128 n][32 k] (both stride GA=36 floats).
// ---------------------------------------------------------------------------
#define GA 36
#define A_FLOATS (128 * GA)                 // 4608
#define STG_FLOATS (2 * A_FLOATS)           // 9216 (A then B)
#define STG_BYTES (STG_FLOATS * 4)          // 36864
#define GEMM_SMEM (3 * STG_BYTES)           // 110592

__device__ __forceinline__ void gemm128(
    float* sm, const float* __restrict__ Ab, const float* __restrict__ Bb,
    float c[2][8][4])
{
    const int tid  = threadIdx.x;
    const int lane = tid & 31;
    const int w    = tid >> 5;
    const int wm   = w >> 1;
    const int wn   = w & 1;

    const int arow = tid >> 3, ac4 = tid & 7;   // staging: rows arow+i*32

    uint32_t smb;
    asm("{ .reg .u64 u; cvta.to.shared.u64 u, %1; cvt.u32.u64 %0, u; }"
        : "=r"(smb) : "l"(sm));
    const uint32_t sa = smb + arow * (GA * 4) + ac4 * 16;
    const uint32_t sb = sa + A_FLOATS * 4;

    // ldmatrix lane address offsets (bytes within tile):
    //  A matrices j=lane>>3: row=(lane&7)+8*((lane>>3)&1), half=lane>>4
    //   -> d0=A[g][t], d1=A[8+g][t], d2=A[g][t+4], d3=A[8+g][t+4]
    //  B matrices: row=(lane&7)+8*(lane>>4), half=(lane>>3)&1
    //   -> d0=B'[g][t], d1=B'[g][t+4], d2=B'[8+g][t], d3=B'[8+g][t+4]
    const int l7 = lane & 7, l8 = (lane >> 3) & 1, l16 = lane >> 4;
    const uint32_t a_loff = (uint32_t)(((l7 + 8 * l8) * GA + l16 * 4) * 4);
    const uint32_t b_loff = (uint32_t)(((l7 + 8 * l16) * GA + l8 * 4) * 4);

    // prologue: stages 0,1
#pragma unroll
    for (int s = 0; s < 2; s++) {
        const int k0 = s * 32;
        const uint32_t so = (uint32_t)(s * STG_BYTES);
#pragma unroll
        for (int i = 0; i < 4; i++) {
            cp16(sa + so + i * 32 * (GA * 4), Ab + (size_t)(arow + i * 32) * DM + k0 + ac4 * 4);
            cp16(sb + so + i * 32 * (GA * 4), Bb + (size_t)(arow + i * 32) * DM + k0 + ac4 * 4);
        }
        CP_COMMIT();
    }

    for (int it = 0; it < 32; it++) {
        if (it < 31) { CP_WAIT(1); } else { CP_WAIT(0); }
        __syncthreads();
        if (it + 2 < 32) {
            const int k0 = (it + 2) * 32;
            const uint32_t so = (uint32_t)(((it + 2) % 3) * STG_BYTES);
#pragma unroll
            for (int i = 0; i < 4; i++) {
                cp16(sa + so + i * 32 * (GA * 4), Ab + (size_t)(arow + i * 32) * DM + k0 + ac4 * 4);
                cp16(sb + so + i * 32 * (GA * 4), Bb + (size_t)(arow + i * 32) * DM + k0 + ac4 * 4);
            }
            CP_COMMIT();
        }

        const uint32_t As32 = smb + (uint32_t)((it % 3) * STG_BYTES);
        const uint32_t Bs32 = As32 + A_FLOATS * 4;
#pragma unroll
        for (int ks = 0; ks < 4; ks++) {
            uint32_t a[2][4];
#pragma unroll
            for (int mt = 0; mt < 2; mt++)
                ldsm4(a[mt][0], a[mt][1], a[mt][2], a[mt][3],
                      As32 + (uint32_t)(((wm * 32 + mt * 16) * GA + ks * 8) * 4) + a_loff);
            uint32_t bf[8][2];
#pragma unroll
            for (int blk = 0; blk < 4; blk++) {
                uint32_t d0, d1, d2, d3;
                ldsm4(d0, d1, d2, d3,
                      Bs32 + (uint32_t)(((wn * 64 + blk * 16) * GA + ks * 8) * 4) + b_loff);
                bf[2*blk][0] = d0; bf[2*blk][1] = d1;
                bf[2*blk+1][0] = d2; bf[2*blk+1][1] = d3;
            }
#pragma unroll
            for (int nt = 0; nt < 8; nt++)
#pragma unroll
                for (int mt = 0; mt < 2; mt++)
                    mma_tf32(c[mt][nt], a[mt][0], a[mt][1], a[mt][2], a[mt][3],
                             bf[nt][0], bf[nt][1]);
        }
    }
}

// ---------------------------------------------------------------------------
// QKV: block 128 m-rows x 2 heads; epilogue writes tf32-rounded (c+bias)
// ---------------------------------------------------------------------------
__global__ __launch_bounds__(256, 2) void qkv_kernel(
    const float* __restrict__ Qb, const float* __restrict__ Kb,
    const float* __restrict__ Vb)
{
    extern __shared__ float sm[];
    const int m0    = blockIdx.x * 128;
    const int hp    = blockIdx.y;
    const int which = blockIdx.z;

    const float* bias = (which == 0 ? Qb : which == 1 ? Kb : Vb);
    float* Out        = (which == 0 ? g_q : which == 1 ? g_k : g_v);
    const float* Bt   = g_wrt + (size_t)which * DM * DM + (size_t)hp * 128 * DM;

    float c[2][8][4];
#pragma unroll
    for (int mt = 0; mt < 2; mt++)
#pragma unroll
        for (int nt = 0; nt < 8; nt++)
#pragma unroll
            for (int i = 0; i < 4; i++) c[mt][nt][i] = 0.f;

    gemm128(sm, g_xr + (size_t)m0 * DM, Bt, c);

    const int tid  = threadIdx.x;
    const int lane = tid & 31;
    const int w    = tid >> 5;
    const int wm   = w >> 1, wn = w & 1;
    const int g    = lane >> 2, t = lane & 3;

    const int h = 2 * hp + wn;
    const float* bi = bias + h * DH;
#pragma unroll
    for (int mt = 0; mt < 2; mt++) {
        int m = m0 + wm * 32 + mt * 16 + g;
        int b_ = m >> 11, p = m & 2047;
        float* dst = Out + (((size_t)(b_ * NH + h)) * SEQ + p) * DH;
#pragma unroll
        for (int nt = 0; nt < 8; nt++) {
            int d = nt * 8 + 2 * t;
            float bx = bi[d], by = bi[d + 1];
            float2 v0 = { f2tff(c[mt][nt][0] + bx), f2tff(c[mt][nt][1] + by) };
            float2 v1 = { f2tff(c[mt][nt][2] + bx), f2tff(c[mt][nt][3] + by) };
            *(float2*)&dst[d]          = v0;
            *(float2*)&dst[8 * DH + d] = v1;
        }
    }
}

// ---------------------------------------------------------------------------
// O-proj: block 128x128; final output fp32
// ---------------------------------------------------------------------------
__global__ __launch_bounds__(256, 2) void oproj_kernel(
    const float* __restrict__ Ob, float* __restrict__ out)
{
    extern __shared__ float sm[];
    const int m0 = blockIdx.x * 128;
    const int n0 = blockIdx.y * 128;

    float c[2][8][4];
#pragma unroll
    for (int mt = 0; mt < 2; mt++)
#pragma unroll
        for (int nt = 0; nt < 8; nt++)
#pragma unroll
            for (int i = 0; i < 4; i++) c[mt][nt][i] = 0.f;

    gemm128(sm, g_o + (size_t)m0 * DM, g_owt + (size_t)n0 * DM, c);

    const int tid  = threadIdx.x;
    const int lane = tid & 31;
    const int w    = tid >> 5;
    const int wm   = w >> 1, wn = w & 1;
    const int g    = lane >> 2, t = lane & 3;

#pragma unroll
    for (int mt = 0; mt < 2; mt++) {
        int m = m0 + wm * 32 + mt * 16 + g;
        float* dst = out + (size_t)m * DM + n0 + wn * 64;
        const float* bi = Ob + n0 + wn * 64;
#pragma unroll
        for (int nt = 0; nt < 8; nt++) {
            int d = nt * 8 + 2 * t;
            float bx = bi[d], by = bi[d + 1];
            float2 v0 = { c[mt][nt][0] + bx, c[mt][nt][1] + by };
            float2 v1 = { c[mt][nt][2] + bx, c[mt][nt][3] + by };
            *(float2*)&dst[d]          = v0;
            *(float2*)&dst[8 * DM + d] = v1;
        }
    }
}

// ---------------------------------------------------------------------------
// Causal flash attention: R12 verbatim (3-stage cp.async, wait->sync->issue)
// ---------------------------------------------------------------------------
#define KSF 68
#define VSF 72
#define KV_FLOATS (64 * KSF + 64 * VSF)
#define KV_BYTES (KV_FLOATS * 4)
#define ATTN_SMEM (3 * KV_BYTES)

__global__ __launch_bounds__(256, 2) void attn_kernel()
{
    extern __shared__ float sm[];

    const int qt = (SEQ / 128 - 1) - blockIdx.x;
    const int bh = blockIdx.y;
    const int q0 = qt * 128;
    const int b  = bh / NH, h = bh % NH;

    const float* qp = g_q + (size_t)bh * SEQ * DH;
    const float* kp = g_k + (size_t)bh * SEQ * DH;
    const float* vp = g_v + (size_t)bh * SEQ * DH;

    const int tid  = threadIdx.x;
    const int lane = tid & 31;
    const int w    = tid >> 5;
    const int g    = lane >> 2;
    const int t    = lane & 3;

    uint32_t smb;
    asm("{ .reg .u64 u; cvta.to.shared.u64 u, %1; cvt.u32.u64 %0, u; }"
        : "=r"(smb) : "l"(sm));

    const int ldr = tid >> 4, ldc = tid & 15;
    const uint32_t kdst = smb + ldr * (KSF * 4) + ldc * 16;
    const uint32_t vdst = smb + 64 * KSF * 4 + ldr * (VSF * 4) + ldc * 16;

    const int nkt = q0 / 64 + 2;

#pragma unroll
    for (int s = 0; s < 2; s++) {
        const int k0 = s * 64;
        const uint32_t so = (uint32_t)(s * KV_BYTES);
#pragma unroll
        for (int i = 0; i < 4; i++) {
            int row = ldr + i * 16;
            cp16(kdst + so + i * 16 * (KSF * 4), kp + (size_t)(k0 + row) * DH + ldc * 4);
            cp16(vdst + so + i * 16 * (VSF * 4), vp + (size_t)(k0 + row) * DH + ldc * 4);
        }
        CP_COMMIT();
    }

    uint32_t qa[8][4];
    {
        const float* qr0 = qp + (size_t)(q0 + w * 16 + g) * DH;
        const float* qr1 = qr0 + 8 * DH;
#pragma unroll
        for (int kt = 0; kt < 8; kt++) {
            qa[kt][0] = __float_as_uint(qr0[kt * 8 + t] * 0.125f);
            qa[kt][1] = __float_as_uint(qr1[kt * 8 + t] * 0.125f);
            qa[kt][2] = __float_as_uint(qr0[kt * 8 + t + 4] * 0.125f);
            qa[kt][3] = __float_as_uint(qr1[kt * 8 + t + 4] * 0.125f);
        }
    }

    float o[8][4];
#pragma unroll
    for (int nt = 0; nt < 8; nt++) { o[nt][0]=o[nt][1]=o[nt][2]=o[nt][3]=0.f; }
    float m0r = -1e30f, m1r = -1e30f, l0 = 0.f, l1 = 0.f;
    const int row0 = q0 + w * 16 + g, row1 = row0 + 8;

    for (int kt2 = 0; kt2 < nkt; kt2++) {
        const int k0 = kt2 * 64;
        if (kt2 + 1 < nkt) { CP_WAIT(1); } else { CP_WAIT(0); }
        __syncthreads();
        if (kt2 + 2 < nkt) {
            const int kn = (kt2 + 2) * 64;
            const uint32_t so = (uint32_t)(((kt2 + 2) % 3) * KV_BYTES);
#pragma unroll
            for (int i = 0; i < 4; i++) {
                int row = ldr + i * 16;
                cp16(kdst + so + i * 16 * (KSF * 4), kp + (size_t)(kn + row) * DH + ldc * 4);
                cp16(vdst + so + i * 16 * (VSF * 4), vp + (size_t)(kn + row) * DH + ldc * 4);
            }
            CP_COMMIT();
        }

        const float* Ks = sm + (kt2 % 3) * KV_FLOATS;
        const float* Vs = Ks + 64 * KSF;

        float s[8][4];
#pragma unroll
        for (int nt = 0; nt < 8; nt++) { s[nt][0]=s[nt][1]=s[nt][2]=s[nt][3]=0.f; }
#pragma unroll
        for (int kt = 0; kt < 8; kt++)
#pragma unroll
            for (int nt = 0; nt < 8; nt++) {
                uint32_t b0 = __float_as_uint(Ks[(nt * 8 + g) * KSF + kt * 8 + t]);
                uint32_t b1 = __float_as_uint(Ks[(nt * 8 + g) * KSF + kt * 8 + t + 4]);
                mma_tf32(s[nt], qa[kt][0], qa[kt][1], qa[kt][2], qa[kt][3], b0, b1);
            }

        if (k0 + 63 > q0) {
#pragma unroll
            for (int nt = 0; nt < 8; nt++) {
                int col = k0 + nt * 8 + 2 * t;
                if (col > row0)     s[nt][0] = -1e30f;
                if (col + 1 > row0) s[nt][1] = -1e30f;
                if (col > row1)     s[nt][2] = -1e30f;
                if (col + 1 > row1) s[nt][3] = -1e30f;
            }
        }

        float mx0 = -1e30f, mx1 = -1e30f;
#pragma unroll
        for (int nt = 0; nt < 8; nt++) {
            mx0 = fmaxf(mx0, fmaxf(s[nt][0], s[nt][1]));
            mx1 = fmaxf(mx1, fmaxf(s[nt][2], s[nt][3]));
        }
        mx0 = fmaxf(mx0, __shfl_xor_sync(~0u, mx0, 1));
        mx0 = fmaxf(mx0, __shfl_xor_sync(~0u, mx0, 2));
        mx1 = fmaxf(mx1, __shfl_xor_sync(~0u, mx1, 1));
        mx1 = fmaxf(mx1, __shfl_xor_sync(~0u, mx1, 2));

        const float m0n = fmaxf(m0r, mx0), m1n = fmaxf(m1r, mx1);
        const float sc0 = __expf(m0r - m0n), sc1 = __expf(m1r - m1n);
        m0r = m0n; m1r = m1n;

        float r0 = 0.f, r1 = 0.f;
#pragma unroll
        for (int nt = 0; nt < 8; nt++) {
            s[nt][0] = __expf(s[nt][0] - m0n); s[nt][1] = __expf(s[nt][1] - m0n);
            s[nt][2] = __expf(s[nt][2] - m1n); s[nt][3] = __expf(s[nt][3] - m1n);
            r0 += s[nt][0] + s[nt][1]; r1 += s[nt][2] + s[nt][3];
        }
        r0 += __shfl_xor_sync(~0u, r0, 1); r0 += __shfl_xor_sync(~0u, r0, 2);
        r1 += __shfl_xor_sync(~0u, r1, 1); r1 += __shfl_xor_sync(~0u, r1, 2);
        l0 = l0 * sc0 + r0; l1 = l1 * sc1 + r1;

#pragma unroll
        for (int nt = 0; nt < 8; nt++) {
            o[nt][0] *= sc0; o[nt][1] *= sc0; o[nt][2] *= sc1; o[nt][3] *= sc1;
        }

        const int s0l = (lane & ~3) | (t >> 1), s1l = s0l + 2;
        const bool e = (t & 1);
#pragma unroll
        for (int kt = 0; kt < 8; kt++) {
            float v00 = __shfl_sync(~0u, s[kt][0], s0l), v01 = __shfl_sync(~0u, s[kt][1], s0l);
            float v10 = __shfl_sync(~0u, s[kt][2], s0l), v11 = __shfl_sync(~0u, s[kt][3], s0l);
            float w00 = __shfl_sync(~0u, s[kt][0], s1l), w01 = __shfl_sync(~0u, s[kt][1], s1l);
            float w10 = __shfl_sync(~0u, s[kt][2], s1l), w11 = __shfl_sync(~0u, s[kt][3], s1l);
            uint32_t pa0 = f2tf(e ? v01 : v00), pa1 = f2tf(e ? v11 : v10);
            uint32_t pa2 = f2tf(e ? w01 : w00), pa3 = f2tf(e ? w11 : w10);
#pragma unroll
            for (int nt = 0; nt < 8; nt++) {
                uint32_t b0 = __float_as_uint(Vs[(kt * 8 + t) * VSF + nt * 8 + g]);
                uint32_t b1 = __float_as_uint(Vs[(kt * 8 + t + 4) * VSF + nt * 8 + g]);
                mma_tf32(o[nt], pa0, pa1, pa2, pa3, b0, b1);
            }
        }
    }

    const float inv0 = 1.f / l0, inv1 = 1.f / l1;
    float* or0 = g_o + ((size_t)(b * SEQ) + row0) * DM + h * DH;
    float* or1 = or0 + (size_t)8 * DM;
#pragma unroll
    for (int nt = 0; nt < 8; nt++) {
        int col = nt * 8 + 2 * t;
        float2 v0 = { f2tff(o[nt][0] * inv0), f2tff(o[nt][1] * inv0) };
        float2 v1 = { f2tff(o[nt][2] * inv1), f2tff(o[nt][3] * inv1) };
        *(float2*)&or0[col] = v0;
        *(float2*)&or1[col] = v1;
    }
}

extern "C" void kernel_launch(void* const* d_in, const int* in_sizes, int n_in,
                              void* d_out, int out_size)
{
    const float* x  = (const float*)d_in[0];
    const float* Qw = (const float*)d_in[1];
    const float* Qb = (const float*)d_in[2];
    const float* Kw = (const float*)d_in[3];
    const float* Kb = (const float*)d_in[4];
    const float* Vw = (const float*)d_in[5];
    const float* Vb = (const float*)d_in[6];
    const float* Ow = (const float*)d_in[7];
    const float* Ob = (const float*)d_in[8];
    float* out = (float*)d_out;

    static int s_init = 0;
    if (!s_init) {
        cudaFuncSetAttribute(attn_kernel,
            cudaFuncAttributeMaxDynamicSharedMemorySize, ATTN_SMEM);
        cudaFuncSetAttribute(qkv_kernel,
            cudaFuncAttributeMaxDynamicSharedMemorySize, GEMM_SMEM);
        cudaFuncSetAttribute(oproj_kernel,
            cudaFuncAttributeMaxDynamicSharedMemorySize, GEMM_SMEM);
        s_init = 1;
    }

    prep_x<<<256, 256>>>(x);
    prep_w<<<dim3(32, 32, 49), 256>>>(Qw, Kw, Vw, Ow);
    qkv_kernel<<<dim3(MROWS / 128, NH / 2, 3), 256, GEMM_SMEM>>>(Qb, Kb, Vb);
    attn_kernel<<<dim3(SEQ / 128, BATCH * NH), 256, ATTN_SMEM>>>();
    oproj_kernel<<<dim3(MROWS / 128, DM / 128), 256, GEMM_SMEM>>>(Ob, out);
}

// round 14
// speedup vs baseline: 1.5164x; 1.5164x over previous
#include <cuda_runtime.h>
#include <cstdint>

#define BATCH 4
#define SEQ   2048
#define NH    16
#define DH    64
#define DM    1024
#define MROWS (BATCH*SEQ)

__device__ float g_q[(size_t)BATCH*NH*SEQ*DH];
__device__ float g_k[(size_t)BATCH*NH*SEQ*DH];
__device__ float g_v[(size_t)BATCH*NH*SEQ*DH];
__device__ float g_o[(size_t)MROWS*DM];
__device__ float g_xr[(size_t)MROWS*DM];      // rounded X
__device__ float g_wr[(size_t)3*NH*DM*DH];    // rounded QKV weights
__device__ float g_owr[(size_t)DM*DM];        // rounded O weights

__device__ __forceinline__ uint32_t f2tf(float x) {
    uint32_t u;
    asm("cvt.rna.tf32.f32 %0, %1;" : "=r"(u) : "f"(x));
    return u;
}
__device__ __forceinline__ float f2tff(float x) { return __uint_as_float(f2tf(x)); }

__device__ __forceinline__ void mma_tf32(float* c,
    uint32_t a0, uint32_t a1, uint32_t a2, uint32_t a3,
    uint32_t b0, uint32_t b1)
{
    asm volatile(
        "mma.sync.aligned.m16n8k8.row.col.f32.tf32.tf32.f32 "
        "{%0,%1,%2,%3}, {%4,%5,%6,%7}, {%8,%9}, {%0,%1,%2,%3};"
        : "+f"(c[0]), "+f"(c[1]), "+f"(c[2]), "+f"(c[3])
        : "r"(a0), "r"(a1), "r"(a2), "r"(a3), "r"(b0), "r"(b1));
}

__device__ __forceinline__ void cp16(uint32_t sdst, const float* gsrc) {
    asm volatile("cp.async.cg.shared.global [%0], [%1], 16;"
                 :: "r"(sdst), "l"(gsrc) : "memory");
}
#define CP_COMMIT() asm volatile("cp.async.commit_group;" ::: "memory")
#define CP_WAIT(n)  asm volatile("cp.async.wait_group %0;" :: "n"(n) : "memory")

// ---------------------------------------------------------------------------
// prep: round inputs to tf32 once (idempotent; numerics identical to in-loop)
// ---------------------------------------------------------------------------
__global__ __launch_bounds__(256) void prep_kernel(
    const float* __restrict__ X,
    const float* __restrict__ Qw, const float* __restrict__ Kw,
    const float* __restrict__ Vw, const float* __restrict__ Ow)
{
    const int z = blockIdx.z;
    const float* src; float* dst; size_t n;
    if (z == 0)      { src = X;  dst = g_xr;  n = (size_t)MROWS * DM; }
    else if (z == 4) { src = Ow; dst = g_owr; n = (size_t)DM * DM; }
    else {
        src = (z == 1 ? Qw : z == 2 ? Kw : Vw);
        dst = g_wr + (size_t)(z - 1) * NH * DM * DH;
        n = (size_t)NH * DM * DH;
    }
    const size_t stride = (size_t)gridDim.x * blockDim.x * 4;
    for (size_t i = ((size_t)blockIdx.x * blockDim.x + threadIdx.x) * 4; i < n; i += stride) {
        float4 v = *(const float4*)&src[i];
        v.x = f2tff(v.x); v.y = f2tff(v.y); v.z = f2tff(v.z); v.w = f2tff(v.w);
        *(float4*)&dst[i] = v;
    }
}

// ---------------------------------------------------------------------------
// GEMM: block 128x128, warp 32x64, 3-stage cp.async, wait -> sync -> issue.
// ---------------------------------------------------------------------------
#define GA 36
#define GB 136
#define A_FLOATS (128 * GA)                 // 4608
#define STG_FLOATS (A_FLOATS + 32 * GB)     // 8960
#define STG_BYTES (STG_FLOATS * 4)          // 35840
#define GEMM_SMEM (3 * STG_BYTES)           // 107520

__device__ __forceinline__ void gemm128(
    float* sm, const float* __restrict__ Ab, const float* __restrict__ Bb,
    int bstride, float c[2][8][4])
{
    const int tid  = threadIdx.x;
    const int lane = tid & 31;
    const int w    = tid >> 5;
    const int wm   = w >> 1;
    const int wn   = w & 1;
    const int g    = lane >> 2;
    const int t    = lane & 3;

    const int arow = tid >> 3, ac4 = tid & 7;
    const int brow = tid >> 5;

    uint32_t smb;
    asm("{ .reg .u64 u; cvta.to.shared.u64 u, %1; cvt.u32.u64 %0, u; }"
        : "=r"(smb) : "l"(sm));
    const uint32_t sa = smb + arow * (GA * 4) + ac4 * 16;
    const uint32_t sb = smb + A_FLOATS * 4 + brow * (GB * 4) + (tid & 31) * 16;

    // prologue: stages 0,1
#pragma unroll
    for (int s = 0; s < 2; s++) {
        const int k0 = s * 32;
        const uint32_t so = (uint32_t)(s * STG_BYTES);
#pragma unroll
        for (int i = 0; i < 4; i++)
            cp16(sa + so + i * 32 * (GA * 4), Ab + (size_t)(arow + i * 32) * DM + k0 + ac4 * 4);
#pragma unroll
        for (int i = 0; i < 4; i++)
            cp16(sb + so + i * 8 * (GB * 4), Bb + (size_t)(k0 + brow + i * 8) * bstride);
        CP_COMMIT();
    }

    for (int it = 0; it < 32; it++) {
        // 1) own-thread completion of stage it
        if (it < 31) { CP_WAIT(1); } else { CP_WAIT(0); }
        // 2) cross-thread visibility
        __syncthreads();
        // 3) refill buffer (it-1)%3 with stage it+2
        if (it + 2 < 32) {
            const int k0 = (it + 2) * 32;
            const uint32_t so = (uint32_t)(((it + 2) % 3) * STG_BYTES);
#pragma unroll
            for (int i = 0; i < 4; i++)
                cp16(sa + so + i * 32 * (GA * 4), Ab + (size_t)(arow + i * 32) * DM + k0 + ac4 * 4);
#pragma unroll
            for (int i = 0; i < 4; i++)
                cp16(sb + so + i * 8 * (GB * 4), Bb + (size_t)(k0 + brow + i * 8) * bstride);
            CP_COMMIT();
        }
        // 4) compute stage it
        const float* As = sm + (it % 3) * STG_FLOATS;
        const float* Bs = As + A_FLOATS;
#pragma unroll
        for (int ks = 0; ks < 4; ks++) {
            uint32_t a[2][4];
#pragma unroll
            for (int mt = 0; mt < 2; mt++) {
                const float* ar = As + (wm * 32 + mt * 16 + g) * GA + ks * 8;
                a[mt][0] = __float_as_uint(ar[t]);
                a[mt][1] = __float_as_uint(ar[8 * GA + t]);
                a[mt][2] = __float_as_uint(ar[t + 4]);
                a[mt][3] = __float_as_uint(ar[8 * GA + t + 4]);
            }
#pragma unroll
            for (int nt = 0; nt < 8; nt++) {
                const float* br = Bs + (ks * 8 + t) * GB + wn * 64 + nt * 8 + g;
                uint32_t b0 = __float_as_uint(br[0]);
                uint32_t b1 = __float_as_uint(br[4 * GB]);
#pragma unroll
                for (int mt = 0; mt < 2; mt++)
                    mma_tf32(c[mt][nt], a[mt][0], a[mt][1], a[mt][2], a[mt][3], b0, b1);
            }
        }
    }
}

// ---------------------------------------------------------------------------
// QKV: block 128 m-rows x 2 heads; epilogue writes tf32-rounded (c+bias)
// ---------------------------------------------------------------------------
__global__ __launch_bounds__(256, 2) void qkv_kernel(
    const float* __restrict__ Qb, const float* __restrict__ Kb,
    const float* __restrict__ Vb)
{
    extern __shared__ float sm[];
    const int m0    = blockIdx.x * 128;
    const int hp    = blockIdx.y;
    const int which = blockIdx.z;

    const float* bias = (which == 0 ? Qb : which == 1 ? Kb : Vb);
    float* Out        = (which == 0 ? g_q : which == 1 ? g_k : g_v);
    const float* W    = g_wr + (size_t)which * NH * DM * DH;

    const int bc4 = threadIdx.x & 31;
    const int bhh = 2 * hp + (bc4 >> 4);
    const float* Bb = W + (size_t)bhh * DM * DH + (bc4 & 15) * 4;

    float c[2][8][4];
#pragma unroll
    for (int mt = 0; mt < 2; mt++)
#pragma unroll
        for (int nt = 0; nt < 8; nt++)
#pragma unroll
            for (int i = 0; i < 4; i++) c[mt][nt][i] = 0.f;

    gemm128(sm, g_xr + (size_t)m0 * DM, Bb, DH, c);

    const int tid  = threadIdx.x;
    const int lane = tid & 31;
    const int w    = tid >> 5;
    const int wm   = w >> 1, wn = w & 1;
    const int g    = lane >> 2, t = lane & 3;

    const int h = 2 * hp + wn;
    const float* bi = bias + h * DH;
#pragma unroll
    for (int mt = 0; mt < 2; mt++) {
        int m = m0 + wm * 32 + mt * 16 + g;
        int b_ = m >> 11, p = m & 2047;
        float* dst = Out + (((size_t)(b_ * NH + h)) * SEQ + p) * DH;
#pragma unroll
        for (int nt = 0; nt < 8; nt++) {
            int d = nt * 8 + 2 * t;
            float bx = bi[d], by = bi[d + 1];
            float2 v0 = { f2tff(c[mt][nt][0] + bx), f2tff(c[mt][nt][1] + by) };
            float2 v1 = { f2tff(c[mt][nt][2] + bx), f2tff(c[mt][nt][3] + by) };
            *(float2*)&dst[d]          = v0;
            *(float2*)&dst[8 * DH + d] = v1;
        }
    }
}

// ---------------------------------------------------------------------------
// O-proj: block 128x128; final output fp32 (no rounding)
// ---------------------------------------------------------------------------
__global__ __launch_bounds__(256, 2) void oproj_kernel(
    const float* __restrict__ Ob, float* __restrict__ out)
{
    extern __shared__ float sm[];
    const int m0 = blockIdx.x * 128;
    const int n0 = blockIdx.y * 128;

    const float* Bb = g_owr + n0 + (threadIdx.x & 31) * 4;

    float c[2][8][4];
#pragma unroll
    for (int mt = 0; mt < 2; mt++)
#pragma unroll
        for (int nt = 0; nt < 8; nt++)
#pragma unroll
            for (int i = 0; i < 4; i++) c[mt][nt][i] = 0.f;

    gemm128(sm, g_o + (size_t)m0 * DM, Bb, DM, c);

    const int tid  = threadIdx.x;
    const int lane = tid & 31;
    const int w    = tid >> 5;
    const int wm   = w >> 1, wn = w & 1;
    const int g    = lane >> 2, t = lane & 3;

#pragma unroll
    for (int mt = 0; mt < 2; mt++) {
        int m = m0 + wm * 32 + mt * 16 + g;
        float* dst = out + (size_t)m * DM + n0 + wn * 64;
        const float* bi = Ob + n0 + wn * 64;
#pragma unroll
        for (int nt = 0; nt < 8; nt++) {
            int d = nt * 8 + 2 * t;
            float bx = bi[d], by = bi[d + 1];
            float2 v0 = { c[mt][nt][0] + bx, c[mt][nt][1] + by };
            float2 v1 = { c[mt][nt][2] + bx, c[mt][nt][3] + by };
            *(float2*)&dst[d]          = v0;
            *(float2*)&dst[8 * DM + d] = v1;
        }
    }
}

// ---------------------------------------------------------------------------
// Causal flash attention: tf32 mma, 3-stage cp.async K/V, wait -> sync -> issue
// ---------------------------------------------------------------------------
#define KSF 68
#define VSF 72
#define KV_FLOATS (64 * KSF + 64 * VSF)    // 8960
#define KV_BYTES (KV_FLOATS * 4)           // 35840
#define ATTN_SMEM (3 * KV_BYTES)           // 107520

__global__ __launch_bounds__(256, 2) void attn_kernel()
{
    extern __shared__ float sm[];

    const int qt = (SEQ / 128 - 1) - blockIdx.x;
    const int bh = blockIdx.y;
    const int q0 = qt * 128;
    const int b  = bh / NH, h = bh % NH;

    const float* qp = g_q + (size_t)bh * SEQ * DH;
    const float* kp = g_k + (size_t)bh * SEQ * DH;
    const float* vp = g_v + (size_t)bh * SEQ * DH;

    const int tid  = threadIdx.x;
    const int lane = tid & 31;
    const int w    = tid >> 5;
    const int g    = lane >> 2;
    const int t    = lane & 3;

    uint32_t smb;
    asm("{ .reg .u64 u; cvta.to.shared.u64 u, %1; cvt.u32.u64 %0, u; }"
        : "=r"(smb) : "l"(sm));

    const int ldr = tid >> 4, ldc = tid & 15;
    const uint32_t kdst = smb + ldr * (KSF * 4) + ldc * 16;
    const uint32_t vdst = smb + 64 * KSF * 4 + ldr * (VSF * 4) + ldc * 16;

    const int nkt = q0 / 64 + 2;

    // prologue: stages 0,1
#pragma unroll
    for (int s = 0; s < 2; s++) {
        const int k0 = s * 64;
        const uint32_t so = (uint32_t)(s * KV_BYTES);
#pragma unroll
        for (int i = 0; i < 4; i++) {
            int row = ldr + i * 16;
            cp16(kdst + so + i * 16 * (KSF * 4), kp + (size_t)(k0 + row) * DH + ldc * 4);
            cp16(vdst + so + i * 16 * (VSF * 4), vp + (size_t)(k0 + row) * DH + ldc * 4);
        }
        CP_COMMIT();
    }

    // Q fragments (pre-rounded; *0.125 exact)
    uint32_t qa[8][4];
    {
        const float* qr0 = qp + (size_t)(q0 + w * 16 + g) * DH;
        const float* qr1 = qr0 + 8 * DH;
#pragma unroll
        for (int kt = 0; kt < 8; kt++) {
            qa[kt][0] = __float_as_uint(qr0[kt * 8 + t] * 0.125f);
            qa[kt][1] = __float_as_uint(qr1[kt * 8 + t] * 0.125f);
            qa[kt][2] = __float_as_uint(qr0[kt * 8 + t + 4] * 0.125f);
            qa[kt][3] = __float_as_uint(qr1[kt * 8 + t + 4] * 0.125f);
        }
    }

    float o[8][4];
#pragma unroll
    for (int nt = 0; nt < 8; nt++) { o[nt][0]=o[nt][1]=o[nt][2]=o[nt][3]=0.f; }
    float m0r = -1e30f, m1r = -1e30f, l0 = 0.f, l1 = 0.f;
    const int row0 = q0 + w * 16 + g, row1 = row0 + 8;

    for (int kt2 = 0; kt2 < nkt; kt2++) {
        const int k0 = kt2 * 64;
        if (kt2 + 1 < nkt) { CP_WAIT(1); } else { CP_WAIT(0); }
        __syncthreads();
        if (kt2 + 2 < nkt) {
            const int kn = (kt2 + 2) * 64;
            const uint32_t so = (uint32_t)(((kt2 + 2) % 3) * KV_BYTES);
#pragma unroll
            for (int i = 0; i < 4; i++) {
                int row = ldr + i * 16;
                cp16(kdst + so + i * 16 * (KSF * 4), kp + (size_t)(kn + row) * DH + ldc * 4);
                cp16(vdst + so + i * 16 * (VSF * 4), vp + (size_t)(kn + row) * DH + ldc * 4);
            }
            CP_COMMIT();
        }

        const float* Ks = sm + (kt2 % 3) * KV_FLOATS;
        const float* Vs = Ks + 64 * KSF;

        float s[8][4];
#pragma unroll
        for (int nt = 0; nt < 8; nt++) { s[nt][0]=s[nt][1]=s[nt][2]=s[nt][3]=0.f; }
#pragma unroll
        for (int kt = 0; kt < 8; kt++)
#pragma unroll
            for (int nt = 0; nt < 8; nt++) {
                uint32_t b0 = __float_as_uint(Ks[(nt * 8 + g) * KSF + kt * 8 + t]);
                uint32_t b1 = __float_as_uint(Ks[(nt * 8 + g) * KSF + kt * 8 + t + 4]);
                mma_tf32(s[nt], qa[kt][0], qa[kt][1], qa[kt][2], qa[kt][3], b0, b1);
            }

        if (k0 + 63 > q0) {
#pragma unroll
            for (int nt = 0; nt < 8; nt++) {
                int col = k0 + nt * 8 + 2 * t;
                if (col > row0)     s[nt][0] = -1e30f;
                if (col + 1 > row0) s[nt][1] = -1e30f;
                if (col > row1)     s[nt][2] = -1e30f;
                if (col + 1 > row1) s[nt][3] = -1e30f;
            }
        }

        float mx0 = -1e30f, mx1 = -1e30f;
#pragma unroll
        for (int nt = 0; nt < 8; nt++) {
            mx0 = fmaxf(mx0, fmaxf(s[nt][0], s[nt][1]));
            mx1 = fmaxf(mx1, fmaxf(s[nt][2], s[nt][3]));
        }
        mx0 = fmaxf(mx0, __shfl_xor_sync(~0u, mx0, 1));
        mx0 = fmaxf(mx0, __shfl_xor_sync(~0u, mx0, 2));
        mx1 = fmaxf(mx1, __shfl_xor_sync(~0u, mx1, 1));
        mx1 = fmaxf(mx1, __shfl_xor_sync(~0u, mx1, 2));

        const float m0n = fmaxf(m0r, mx0), m1n = fmaxf(m1r, mx1);
        const float sc0 = __expf(m0r - m0n), sc1 = __expf(m1r - m1n);
        m0r = m0n; m1r = m1n;

        float r0 = 0.f, r1 = 0.f;
#pragma unroll
        for (int nt = 0; nt < 8; nt++) {
            s[nt][0] = __expf(s[nt][0] - m0n); s[nt][1] = __expf(s[nt][1] - m0n);
            s[nt][2] = __expf(s[nt][2] - m1n); s[nt][3] = __expf(s[nt][3] - m1n);
            r0 += s[nt][0] + s[nt][1]; r1 += s[nt][2] + s[nt][3];
        }
        r0 += __shfl_xor_sync(~0u, r0, 1); r0 += __shfl_xor_sync(~0u, r0, 2);
        r1 += __shfl_xor_sync(~0u, r1, 1); r1 += __shfl_xor_sync(~0u, r1, 2);
        l0 = l0 * sc0 + r0; l1 = l1 * sc1 + r1;

#pragma unroll
        for (int nt = 0; nt < 8; nt++) {
            o[nt][0] *= sc0; o[nt][1] *= sc0; o[nt][2] *= sc1; o[nt][3] *= sc1;
        }

        const int s0l = (lane & ~3) | (t >> 1), s1l = s0l + 2;
        const bool e = (t & 1);
#pragma unroll
        for (int kt = 0; kt < 8; kt++) {
            float v00 = __shfl_sync(~0u, s[kt][0], s0l), v01 = __shfl_sync(~0u, s[kt][1], s0l);
            float v10 = __shfl_sync(~0u, s[kt][2], s0l), v11 = __shfl_sync(~0u, s[kt][3], s0l);
            float w00 = __shfl_sync(~0u, s[kt][0], s1l), w01 = __shfl_sync(~0u, s[kt][1], s1l);
            float w10 = __shfl_sync(~0u, s[kt][2], s1l), w11 = __shfl_sync(~0u, s[kt][3], s1l);
            uint32_t pa0 = f2tf(e ? v01 : v00), pa1 = f2tf(e ? v11 : v10);
            uint32_t pa2 = f2tf(e ? w01 : w00), pa3 = f2tf(e ? w11 : w10);
#pragma unroll
            for (int nt = 0; nt < 8; nt++) {
                uint32_t b0 = __float_as_uint(Vs[(kt * 8 + t) * VSF + nt * 8 + g]);
                uint32_t b1 = __float_as_uint(Vs[(kt * 8 + t + 4) * VSF + nt * 8 + g]);
                mma_tf32(o[nt], pa0, pa1, pa2, pa3, b0, b1);
            }
        }
    }

    const float inv0 = 1.f / l0, inv1 = 1.f / l1;
    float* or0 = g_o + ((size_t)(b * SEQ) + row0) * DM + h * DH;
    float* or1 = or0 + (size_t)8 * DM;
#pragma unroll
    for (int nt = 0; nt < 8; nt++) {
        int col = nt * 8 + 2 * t;
        float2 v0 = { f2tff(o[nt][0] * inv0), f2tff(o[nt][1] * inv0) };
        float2 v1 = { f2tff(o[nt][2] * inv1), f2tff(o[nt][3] * inv1) };
        *(float2*)&or0[col] = v0;
        *(float2*)&or1[col] = v1;
    }
}

extern "C" void kernel_launch(void* const* d_in, const int* in_sizes, int n_in,
                              void* d_out, int out_size)
{
    const float* x  = (const float*)d_in[0];
    const float* Qw = (const float*)d_in[1];
    const float* Qb = (const float*)d_in[2];
    const float* Kw = (const float*)d_in[3];
    const float* Kb = (const float*)d_in[4];
    const float* Vw = (const float*)d_in[5];
    const float* Vb = (const float*)d_in[6];
    const float* Ow = (const float*)d_in[7];
    const float* Ob = (const float*)d_in[8];
    float* out = (float*)d_out;

    static int s_init = 0;
    if (!s_init) {
        cudaFuncSetAttribute(attn_kernel,
            cudaFuncAttributeMaxDynamicSharedMemorySize, ATTN_SMEM);
        cudaFuncSetAttribute(qkv_kernel,
            cudaFuncAttributeMaxDynamicSharedMemorySize, GEMM_SMEM);
        cudaFuncSetAttribute(oproj_kernel,
            cudaFuncAttributeMaxDynamicSharedMemorySize, GEMM_SMEM);
        s_init = 1;
    }

    prep_kernel<<<dim3(256, 1, 5), 256>>>(x, Qw, Kw, Vw, Ow);
    qkv_kernel<<<dim3(MROWS / 128, NH / 2, 3), 256, GEMM_SMEM>>>(Qb, Kb, Vb);
    attn_kernel<<<dim3(SEQ / 128, BATCH * NH), 256, ATTN_SMEM>>>();
    oproj_kernel<<<dim3(MROWS / 128, DM / 128), 256, GEMM_SMEM>>>(Ob, out);
}